// round 3
// baseline (speedup 1.0000x reference)
#include <cuda_runtime.h>
#include <math.h>

#define HIDDEN 1280
#define HEADS  8
#define DH     160
#define BATCH  2
#define SEQ    4096
#define MROWS  (BATCH*SEQ)   // 8192
#define RANK   4

// ---------------- scratch (device globals; no runtime allocation) ----------
__device__ float g_q[(size_t)MROWS*HIDDEN];
__device__ float g_k[(size_t)MROWS*HIDDEN];
__device__ float g_v[(size_t)MROWS*HIDDEN];
__device__ float g_o[(size_t)MROWS*HIDDEN];

// ---------------- cp.async helpers -----------------------------------------
__device__ __forceinline__ void cp_async16(void* smem_dst, const void* gsrc) {
    unsigned saddr = (unsigned)__cvta_generic_to_shared(smem_dst);
    asm volatile("cp.async.cg.shared.global [%0], [%1], 16;\n"
                 :: "r"(saddr), "l"(gsrc));
}
#define CP_COMMIT() asm volatile("cp.async.commit_group;\n" ::: "memory")
#define CP_WAIT0()  asm volatile("cp.async.wait_group 0;\n" ::: "memory")

// ---------------- SGEMM: C[M,N] = A[M,K] @ B[K,N] (+bias) ------------------
// BM=BN=128, BK=8, 256 threads, 8x8 per thread.
// Double-buffered smem + register-staged prefetch; one barrier per k-iter.
#define BM 128
#define BN 128
#define BKG 8
#define TM 8
#define TN 8

__device__ __forceinline__ void sgemm_body(
    const float* __restrict__ A, const float* __restrict__ B,
    const float* __restrict__ bias, float* __restrict__ C,
    int N, int K)
{
    __shared__ float As[2][BKG][BM];
    __shared__ float Bs[2][BKG][BN];

    const int tid = threadIdx.x;
    const float* Ab = A + (size_t)blockIdx.y * BM * K;
    const float* Bb = B + (size_t)blockIdx.x * BN;
    float* Cb = C + (size_t)blockIdx.y * BM * N + (size_t)blockIdx.x * BN;

    const int aRow = tid >> 1;              // 0..127
    const int aCol = (tid & 1) * 4;         // 0 or 4
    const int bRow = tid >> 5;              // 0..7
    const int bCol = (tid & 31) * 4;        // 0..124

    const int tr = (tid >> 4) * TM;         // 0..120
    const int tc = (tid & 15) * TN;         // 0..120

    float acc[TM][TN];
#pragma unroll
    for (int i = 0; i < TM; i++)
#pragma unroll
        for (int j = 0; j < TN; j++) acc[i][j] = 0.f;

    const int nIter = K / BKG;

    {   // prologue: tile 0 -> buffer 0
        float4 a4 = *(const float4*)(Ab + (size_t)aRow * K + aCol);
        As[0][aCol + 0][aRow] = a4.x;
        As[0][aCol + 1][aRow] = a4.y;
        As[0][aCol + 2][aRow] = a4.z;
        As[0][aCol + 3][aRow] = a4.w;
        float4 b4 = *(const float4*)(Bb + (size_t)bRow * N + bCol);
        *(float4*)&Bs[0][bRow][bCol] = b4;
    }
    __syncthreads();

    for (int it = 0; it < nIter; it++) {
        const int cur = it & 1;
        const int nxt = cur ^ 1;

        float4 a4n, b4n;
        const bool more = (it + 1 < nIter);
        if (more) {
            const int k0 = (it + 1) * BKG;
            a4n = *(const float4*)(Ab + (size_t)aRow * K + k0 + aCol);
            b4n = *(const float4*)(Bb + (size_t)(k0 + bRow) * N + bCol);
        }

#pragma unroll
        for (int kk = 0; kk < BKG; kk++) {
            float rA[TM], rB[TN];
            *(float4*)&rA[0] = *(const float4*)&As[cur][kk][tr];
            *(float4*)&rA[4] = *(const float4*)&As[cur][kk][tr + 4];
            *(float4*)&rB[0] = *(const float4*)&Bs[cur][kk][tc];
            *(float4*)&rB[4] = *(const float4*)&Bs[cur][kk][tc + 4];
#pragma unroll
            for (int i = 0; i < TM; i++)
#pragma unroll
                for (int j = 0; j < TN; j++) acc[i][j] += rA[i] * rB[j];
        }

        if (more) {
            As[nxt][aCol + 0][aRow] = a4n.x;
            As[nxt][aCol + 1][aRow] = a4n.y;
            As[nxt][aCol + 2][aRow] = a4n.z;
            As[nxt][aCol + 3][aRow] = a4n.w;
            *(float4*)&Bs[nxt][bRow][bCol] = b4n;
        }
        __syncthreads();
    }

#pragma unroll
    for (int i = 0; i < TM; i++) {
#pragma unroll
        for (int j = 0; j < TN; j += 4) {
            float4 o;
            o.x = acc[i][j + 0];
            o.y = acc[i][j + 1];
            o.z = acc[i][j + 2];
            o.w = acc[i][j + 3];
            if (bias) {
                int n = blockIdx.x * BN + tc + j;
                o.x += bias[n + 0]; o.y += bias[n + 1];
                o.z += bias[n + 2]; o.w += bias[n + 3];
            }
            *(float4*)(Cb + (size_t)(tr + i) * N + tc + j) = o;
        }
    }
}

// fused QKV projection: grid.z selects weight/output
__global__ __launch_bounds__(256) void sgemm_qkv_kernel(
    const float* __restrict__ x,
    const float* __restrict__ wq, const float* __restrict__ wk,
    const float* __restrict__ wv,
    float* __restrict__ q, float* __restrict__ k, float* __restrict__ v)
{
    const float* B = (blockIdx.z == 0) ? wq : (blockIdx.z == 1) ? wk : wv;
    float* C       = (blockIdx.z == 0) ? q  : (blockIdx.z == 1) ? k  : v;
    sgemm_body(x, B, nullptr, C, HIDDEN, HIDDEN);
}

__global__ __launch_bounds__(256) void sgemm_kernel(
    const float* __restrict__ A, const float* __restrict__ B,
    const float* __restrict__ bias, float* __restrict__ C,
    int M, int N, int K)
{
    sgemm_body(A, B, bias, C, N, K);
}

// ---------------- LoRA rank-4 in-place update: row += (row @ a) @ b --------
__global__ __launch_bounds__(128) void lora_kernel(
    float* __restrict__ kv, const float* __restrict__ a, const float* __restrict__ b)
{
    const int m = blockIdx.x;
    const int tid = threadIdx.x;
    float* row = kv + (size_t)m * HIDDEN;

    float p0 = 0.f, p1 = 0.f, p2 = 0.f, p3 = 0.f;
    for (int d = tid; d < HIDDEN; d += 128) {
        float x = row[d];
        p0 += x * a[d * RANK + 0];
        p1 += x * a[d * RANK + 1];
        p2 += x * a[d * RANK + 2];
        p3 += x * a[d * RANK + 3];
    }
    __shared__ float sm[4][128];
    sm[0][tid] = p0; sm[1][tid] = p1; sm[2][tid] = p2; sm[3][tid] = p3;
    __syncthreads();
    for (int s = 64; s > 0; s >>= 1) {
        if (tid < s) {
            sm[0][tid] += sm[0][tid + s];
            sm[1][tid] += sm[1][tid + s];
            sm[2][tid] += sm[2][tid + s];
            sm[3][tid] += sm[3][tid + s];
        }
        __syncthreads();
    }
    const float t0 = sm[0][0], t1 = sm[1][0], t2 = sm[2][0], t3 = sm[3][0];
    for (int d = tid; d < HIDDEN; d += 128) {
        row[d] += t0 * b[d] + t1 * b[HIDDEN + d]
                + t2 * b[2 * HIDDEN + d] + t3 * b[3 * HIDDEN + d];
    }
}

// ---------------- Flash attention (fp32, cp.async double-buffered KV) ------
// Block: 256 threads handle 64 queries of one (b, h). 4 threads per query,
// each owns 40 of the 160 dims (Q frag + O accum in registers).
// K and V tiles double-buffered in smem; tile t+1 streams in via cp.async
// while tile t is computed. Scores parked in padded smem (stride 65).
#define BQ  64
#define BKT 64
#define SSTRIDE (BKT + 1)
#define TILE_F (BKT * DH)   // 10240 floats per K or V tile
#define ATTN_SMEM_BYTES ((4 * TILE_F + BQ * SSTRIDE) * (int)sizeof(float))

__global__ __launch_bounds__(256) void attn_kernel(
    const float* __restrict__ Q, const float* __restrict__ K,
    const float* __restrict__ V, float* __restrict__ O)
{
    extern __shared__ float smem[];
    float* Ks[2] = { smem,              smem + TILE_F };
    float* Vs[2] = { smem + 2 * TILE_F, smem + 3 * TILE_F };
    float* Ss    = smem + 4 * TILE_F;   // BQ * SSTRIDE

    const int tid = threadIdx.x;
    const int b = blockIdx.z, h = blockIdx.y;
    const int q0 = blockIdx.x * BQ;
    const int q = tid >> 2;            // 0..63
    const int sub = tid & 3;           // 0..3 -> dims [sub*40, sub*40+40)

    const size_t head_off = (size_t)h * DH;
    const float* Qb = Q + ((size_t)(b * SEQ + q0)) * HIDDEN + head_off;
    const float* Kb = K + ((size_t)b * SEQ) * HIDDEN + head_off;
    const float* Vb = V + ((size_t)b * SEQ) * HIDDEN + head_off;

    const float scale = rsqrtf((float)DH);

    float qf[40];
#pragma unroll
    for (int i = 0; i < 10; i++) {
        float4 t = *(const float4*)(Qb + (size_t)q * HIDDEN + sub * 40 + i * 4);
        qf[i * 4 + 0] = t.x * scale;
        qf[i * 4 + 1] = t.y * scale;
        qf[i * 4 + 2] = t.z * scale;
        qf[i * 4 + 3] = t.w * scale;
    }
    float o[40];
#pragma unroll
    for (int i = 0; i < 40; i++) o[i] = 0.f;
    float mrun = -INFINITY, lrun = 0.f;

    const int nT = SEQ / BKT;

    // prologue: issue tile 0 into buffer 0
#pragma unroll 1
    for (int idx = tid; idx < TILE_F / 4; idx += 256) {
        int j = idx / (DH / 4);
        int c = (idx % (DH / 4)) * 4;
        cp_async16(&Ks[0][j * DH + c], Kb + (size_t)j * HIDDEN + c);
        cp_async16(&Vs[0][j * DH + c], Vb + (size_t)j * HIDDEN + c);
    }
    CP_COMMIT();

    for (int t = 0; t < nT; t++) {
        const int cur = t & 1;
        const int nxt = cur ^ 1;

        CP_WAIT0();
        __syncthreads();   // tile t resident; all prior reads of nxt done

        if (t + 1 < nT) {
            const int kv1 = (t + 1) * BKT;
#pragma unroll 1
            for (int idx = tid; idx < TILE_F / 4; idx += 256) {
                int j = idx / (DH / 4);
                int c = (idx % (DH / 4)) * 4;
                cp_async16(&Ks[nxt][j * DH + c],
                           Kb + (size_t)(kv1 + j) * HIDDEN + c);
                cp_async16(&Vs[nxt][j * DH + c],
                           Vb + (size_t)(kv1 + j) * HIDDEN + c);
            }
            CP_COMMIT();
        }

        // scores: each thread partial-dots its 40 dims, shfl-reduce sub group
        const float* Kt = Ks[cur];
        float tmax = -INFINITY;
#pragma unroll 4
        for (int j = 0; j < BKT; j++) {
            const float* kr = &Kt[j * DH + sub * 40];
            float s = 0.f;
#pragma unroll
            for (int i4 = 0; i4 < 10; i4++) {
                float4 k4 = *(const float4*)(kr + i4 * 4);
                s += qf[i4 * 4 + 0] * k4.x;
                s += qf[i4 * 4 + 1] * k4.y;
                s += qf[i4 * 4 + 2] * k4.z;
                s += qf[i4 * 4 + 3] * k4.w;
            }
            s += __shfl_xor_sync(0xffffffffu, s, 1);
            s += __shfl_xor_sync(0xffffffffu, s, 2);
            tmax = fmaxf(tmax, s);
            if (sub == 0) Ss[q * SSTRIDE + j] = s;
        }

        const float mnew = fmaxf(mrun, tmax);
        const float corr = __expf(mrun - mnew);
        lrun *= corr;
#pragma unroll
        for (int i = 0; i < 40; i++) o[i] *= corr;
        mrun = mnew;

        __syncthreads();   // scores visible to all subs

        const float* Vt = Vs[cur];
#pragma unroll 2
        for (int j = 0; j < BKT; j++) {
            float p = __expf(Ss[q * SSTRIDE + j] - mrun);
            lrun += p;
            const float* vr = &Vt[j * DH + sub * 40];
#pragma unroll
            for (int i4 = 0; i4 < 10; i4++) {
                float4 v4 = *(const float4*)(vr + i4 * 4);
                o[i4 * 4 + 0] += p * v4.x;
                o[i4 * 4 + 1] += p * v4.y;
                o[i4 * 4 + 2] += p * v4.z;
                o[i4 * 4 + 3] += p * v4.w;
            }
        }
    }

    const float inv = 1.f / lrun;
    float* Ob = O + ((size_t)(b * SEQ + q0 + q)) * HIDDEN + head_off + sub * 40;
#pragma unroll
    for (int i = 0; i < 10; i++) {
        float4 t;
        t.x = o[i * 4 + 0] * inv;
        t.y = o[i * 4 + 1] * inv;
        t.z = o[i * 4 + 2] * inv;
        t.w = o[i * 4 + 3] * inv;
        *(float4*)(Ob + i * 4) = t;
    }
}

// ---------------- launch ----------------------------------------------------
extern "C" void kernel_launch(void* const* d_in, const int* in_sizes, int n_in,
                              void* d_out, int out_size)
{
    const float* x     = (const float*)d_in[0];
    const float* w_q   = (const float*)d_in[1];
    const float* w_k   = (const float*)d_in[2];
    const float* w_v   = (const float*)d_in[3];
    const float* lka   = (const float*)d_in[4];
    const float* lkb   = (const float*)d_in[5];
    const float* lva   = (const float*)d_in[6];
    const float* lvb   = (const float*)d_in[7];
    const float* w_out = (const float*)d_in[8];
    const float* b_out = (const float*)d_in[9];
    float* out = (float*)d_out;

    float *q_ptr, *k_ptr, *v_ptr, *o_ptr;
    cudaGetSymbolAddress((void**)&q_ptr, g_q);
    cudaGetSymbolAddress((void**)&k_ptr, g_k);
    cudaGetSymbolAddress((void**)&v_ptr, g_v);
    cudaGetSymbolAddress((void**)&o_ptr, g_o);

    cudaFuncSetAttribute(attn_kernel,
                         cudaFuncAttributeMaxDynamicSharedMemorySize,
                         ATTN_SMEM_BYTES);

    // fused QKV projections
    dim3 qkv_grid(HIDDEN / BN, MROWS / BM, 3);
    sgemm_qkv_kernel<<<qkv_grid, 256>>>(x, w_q, w_k, w_v, q_ptr, k_ptr, v_ptr);

    // LoRA rank-4 updates (in place)
    lora_kernel<<<MROWS, 128>>>(k_ptr, lka, lkb);
    lora_kernel<<<MROWS, 128>>>(v_ptr, lva, lvb);

    // Attention
    dim3 agrid(SEQ / BQ, HEADS, BATCH);
    attn_kernel<<<agrid, 256, ATTN_SMEM_BYTES>>>(q_ptr, k_ptr, v_ptr, o_ptr);

    // Output projection + bias
    dim3 ggrid(HIDDEN / BN, MROWS / BM);
    sgemm_kernel<<<ggrid, 256>>>(o_ptr, w_out, b_out, out, MROWS, HIDDEN, HIDDEN);
}

// round 16
// speedup vs baseline: 1.9484x; 1.9484x over previous
#include <cuda_runtime.h>
#include <math.h>

#define HIDDEN 1280
#define HEADS  8
#define DH     160
#define BATCH  2
#define SEQ    4096
#define MROWS  (BATCH*SEQ)   // 8192
#define RANK   4
#define BH     (BATCH*HEADS) // 16

// ---------------- scratch (device globals; no runtime allocation) ----------
__device__ float g_q[(size_t)MROWS*HIDDEN];
__device__ float g_k[(size_t)MROWS*HIDDEN];
__device__ float g_v[(size_t)MROWS*HIDDEN];
__device__ float g_o[(size_t)MROWS*HIDDEN];
// transposed per-head Q,K: [bh][dh][seq]
__device__ float g_qt[(size_t)BH*DH*SEQ];
__device__ float g_kt[(size_t)BH*DH*SEQ];

// ---------------- cp.async helpers -----------------------------------------
__device__ __forceinline__ void cp_async16(void* smem_dst, const void* gsrc) {
    unsigned saddr = (unsigned)__cvta_generic_to_shared(smem_dst);
    asm volatile("cp.async.cg.shared.global [%0], [%1], 16;\n"
                 :: "r"(saddr), "l"(gsrc));
}
#define CP_COMMIT() asm volatile("cp.async.commit_group;\n" ::: "memory")
#define CP_WAIT0()  asm volatile("cp.async.wait_group 0;\n" ::: "memory")
#define CP_WAIT1()  asm volatile("cp.async.wait_group 1;\n" ::: "memory")

// ---------------- SGEMM: C[M,N] = A[M,K] @ B[K,N] (+bias) ------------------
#define BM 128
#define BN 128
#define BKG 8
#define TM 8
#define TN 8

__device__ __forceinline__ void sgemm_body(
    const float* __restrict__ A, const float* __restrict__ B,
    const float* __restrict__ bias, float* __restrict__ C,
    int N, int K)
{
    __shared__ float As[2][BKG][BM];
    __shared__ float Bs[2][BKG][BN];

    const int tid = threadIdx.x;
    const float* Ab = A + (size_t)blockIdx.y * BM * K;
    const float* Bb = B + (size_t)blockIdx.x * BN;
    float* Cb = C + (size_t)blockIdx.y * BM * N + (size_t)blockIdx.x * BN;

    const int aRow = tid >> 1;
    const int aCol = (tid & 1) * 4;
    const int bRow = tid >> 5;
    const int bCol = (tid & 31) * 4;
    const int tr = (tid >> 4) * TM;
    const int tc = (tid & 15) * TN;

    float acc[TM][TN];
#pragma unroll
    for (int i = 0; i < TM; i++)
#pragma unroll
        for (int j = 0; j < TN; j++) acc[i][j] = 0.f;

    const int nIter = K / BKG;
    {
        float4 a4 = *(const float4*)(Ab + (size_t)aRow * K + aCol);
        As[0][aCol + 0][aRow] = a4.x;
        As[0][aCol + 1][aRow] = a4.y;
        As[0][aCol + 2][aRow] = a4.z;
        As[0][aCol + 3][aRow] = a4.w;
        float4 b4 = *(const float4*)(Bb + (size_t)bRow * N + bCol);
        *(float4*)&Bs[0][bRow][bCol] = b4;
    }
    __syncthreads();

    for (int it = 0; it < nIter; it++) {
        const int cur = it & 1;
        const int nxt = cur ^ 1;
        float4 a4n, b4n;
        const bool more = (it + 1 < nIter);
        if (more) {
            const int k0 = (it + 1) * BKG;
            a4n = *(const float4*)(Ab + (size_t)aRow * K + k0 + aCol);
            b4n = *(const float4*)(Bb + (size_t)(k0 + bRow) * N + bCol);
        }
#pragma unroll
        for (int kk = 0; kk < BKG; kk++) {
            float rA[TM], rB[TN];
            *(float4*)&rA[0] = *(const float4*)&As[cur][kk][tr];
            *(float4*)&rA[4] = *(const float4*)&As[cur][kk][tr + 4];
            *(float4*)&rB[0] = *(const float4*)&Bs[cur][kk][tc];
            *(float4*)&rB[4] = *(const float4*)&Bs[cur][kk][tc + 4];
#pragma unroll
            for (int i = 0; i < TM; i++)
#pragma unroll
                for (int j = 0; j < TN; j++) acc[i][j] += rA[i] * rB[j];
        }
        if (more) {
            As[nxt][aCol + 0][aRow] = a4n.x;
            As[nxt][aCol + 1][aRow] = a4n.y;
            As[nxt][aCol + 2][aRow] = a4n.z;
            As[nxt][aCol + 3][aRow] = a4n.w;
            *(float4*)&Bs[nxt][bRow][bCol] = b4n;
        }
        __syncthreads();
    }

#pragma unroll
    for (int i = 0; i < TM; i++) {
#pragma unroll
        for (int j = 0; j < TN; j += 4) {
            float4 o;
            o.x = acc[i][j + 0];
            o.y = acc[i][j + 1];
            o.z = acc[i][j + 2];
            o.w = acc[i][j + 3];
            if (bias) {
                int n = blockIdx.x * BN + tc + j;
                o.x += bias[n + 0]; o.y += bias[n + 1];
                o.z += bias[n + 2]; o.w += bias[n + 3];
            }
            *(float4*)(Cb + (size_t)(tr + i) * N + tc + j) = o;
        }
    }
}

__global__ __launch_bounds__(256) void sgemm_qkv_kernel(
    const float* __restrict__ x,
    const float* __restrict__ wq, const float* __restrict__ wk,
    const float* __restrict__ wv,
    float* __restrict__ q, float* __restrict__ k, float* __restrict__ v)
{
    const float* B = (blockIdx.z == 0) ? wq : (blockIdx.z == 1) ? wk : wv;
    float* C       = (blockIdx.z == 0) ? q  : (blockIdx.z == 1) ? k  : v;
    sgemm_body(x, B, nullptr, C, HIDDEN, HIDDEN);
}

__global__ __launch_bounds__(256) void sgemm_kernel(
    const float* __restrict__ A, const float* __restrict__ B,
    const float* __restrict__ bias, float* __restrict__ C,
    int M, int N, int K)
{
    sgemm_body(A, B, bias, C, N, K);
}

// ---------------- LoRA rank-4 in-place update: row += (row @ a) @ b --------
__global__ __launch_bounds__(128) void lora_kernel(
    float* __restrict__ kv, const float* __restrict__ a, const float* __restrict__ b)
{
    const int m = blockIdx.x;
    const int tid = threadIdx.x;
    float* row = kv + (size_t)m * HIDDEN;

    float p0 = 0.f, p1 = 0.f, p2 = 0.f, p3 = 0.f;
    for (int d = tid; d < HIDDEN; d += 128) {
        float x = row[d];
        p0 += x * a[d * RANK + 0];
        p1 += x * a[d * RANK + 1];
        p2 += x * a[d * RANK + 2];
        p3 += x * a[d * RANK + 3];
    }
    __shared__ float sm[4][128];
    sm[0][tid] = p0; sm[1][tid] = p1; sm[2][tid] = p2; sm[3][tid] = p3;
    __syncthreads();
    for (int s = 64; s > 0; s >>= 1) {
        if (tid < s) {
            sm[0][tid] += sm[0][tid + s];
            sm[1][tid] += sm[1][tid + s];
            sm[2][tid] += sm[2][tid + s];
            sm[3][tid] += sm[3][tid + s];
        }
        __syncthreads();
    }
    const float t0 = sm[0][0], t1 = sm[1][0], t2 = sm[2][0], t3 = sm[3][0];
    for (int d = tid; d < HIDDEN; d += 128) {
        row[d] += t0 * b[d] + t1 * b[HIDDEN + d]
                + t2 * b[2 * HIDDEN + d] + t3 * b[3 * HIDDEN + d];
    }
}

// ---------------- transpose Q,K per head: [s][h*160+c] -> [bh][c][s] --------
__global__ __launch_bounds__(256) void transpose_qk_kernel(
    const float* __restrict__ Qin, const float* __restrict__ Kin,
    float* __restrict__ Qt, float* __restrict__ Kt)
{
    __shared__ float tile[32][33];
    const int zt = blockIdx.z;
    const int bh = zt & (BH - 1);
    const int which = zt >> 4;              // 0 = Q, 1 = K
    const float* in = which ? Kin : Qin;
    float* out = which ? Kt : Qt;
    const float scl = which ? 1.f : rsqrtf((float)DH);
    const int b = bh >> 3, h = bh & 7;
    const int s0 = blockIdx.x * 32, c0 = blockIdx.y * 32;

    for (int r = threadIdx.y; r < 32; r += 8) {
        tile[r][threadIdx.x] =
            in[((size_t)(b * SEQ + s0 + r)) * HIDDEN + h * DH + c0 + threadIdx.x] * scl;
    }
    __syncthreads();
    for (int r = threadIdx.y; r < 32; r += 8) {
        out[((size_t)bh * DH + c0 + r) * SEQ + s0 + threadIdx.x] = tile[threadIdx.x][r];
    }
}

// ---------------- Flash attention v2 (register-blocked smem GEMMs) ---------
// 256 threads, 128 queries of one (b,h). Per 64-key tile:
//   score GEMM: 8q x 4k register tile per thread (FMA-bound: 24 floats/cyc
//               smem demand vs 32 float/cyc crossbar at full FFMA issue)
//   PV GEMM:    8q x 10d register tile per thread
// cp.async split-group pipeline: K and V tiles in separate commit groups;
// K(t+1) overlaps PV(t), V(t+1) overlaps score(t+1).
#define BQA 128
#define BKA 64
#define PSTR 68

#define SM_QS   (DH * BQA)          // 20480
#define SM_KS   (DH * BKA)          // 10240
#define SM_VS   (BKA * DH)          // 10240
#define SM_PS   (BQA * PSTR)        // 8704
#define ATTN_SMEM_F (SM_QS + SM_KS + SM_VS + SM_PS + 2 * BQA)
#define ATTN_SMEM_BYTES (ATTN_SMEM_F * (int)sizeof(float))

__global__ __launch_bounds__(256, 1) void attn_kernel(
    const float* __restrict__ Qt, const float* __restrict__ Kt,
    const float* __restrict__ V, float* __restrict__ O)
{
    extern __shared__ float smp[];
    float* Qs = smp;                       // [DH][BQA]
    float* Ks = Qs + SM_QS;                // [DH][BKA]
    float* Vs = Ks + SM_KS;                // [BKA][DH]
    float* Ps = Vs + SM_VS;                // [BQA][PSTR]
    float* corr_s = Ps + SM_PS;            // [BQA]
    float* l_s = corr_s + BQA;             // [BQA]

    const int tid = threadIdx.x;
    const int bh = blockIdx.y;
    const int q0 = blockIdx.x * BQA;
    const int b = bh >> 3, h = bh & 7;

    const int ty = tid >> 4;               // 0..15: q rows ty*8..+8
    const int tx = tid & 15;               // 0..15: k cols tx*4 / d cols tx*10

    const float* Qg = Qt + (size_t)bh * DH * SEQ + q0;
    const float* Kg = Kt + (size_t)bh * DH * SEQ;
    const float* Vg = V + (size_t)b * SEQ * HIDDEN + h * DH;

    // prologue: group A = {Q tile, K tile 0}; group B = {V tile 0}
#pragma unroll
    for (int i = 0; i < 20; i++) {
        int idx = tid + 256 * i;
        int c = idx >> 5, col = (idx & 31) * 4;
        cp_async16(&Qs[c * BQA + col], Qg + (size_t)c * SEQ + col);
    }
#pragma unroll
    for (int i = 0; i < 10; i++) {
        int idx = tid + 256 * i;
        int c = idx >> 4, col = (idx & 15) * 4;
        cp_async16(&Ks[c * BKA + col], Kg + (size_t)c * SEQ + col);
    }
    CP_COMMIT();
#pragma unroll
    for (int i = 0; i < 10; i++) {
        int idx = tid + 256 * i;
        int j = idx / 40, col = (idx % 40) * 4;
        cp_async16(&Vs[j * DH + col], Vg + (size_t)j * HIDDEN + col);
    }
    CP_COMMIT();

    float m_run[8], l_run[8];
    float o[8][10];
#pragma unroll
    for (int qi = 0; qi < 8; qi++) {
        m_run[qi] = -INFINITY;
        l_run[qi] = 0.f;
#pragma unroll
        for (int d = 0; d < 10; d++) o[qi][d] = 0.f;
    }

    const int nT = SEQ / BKA;              // 64

    for (int t = 0; t < nT; t++) {
        // wait for K(t) only (V(t) group committed after it may still fly)
        CP_WAIT1();
        __syncthreads();

        // ---- score GEMM: s[8][4] += Qs[c][q..] * Ks[c][k..] ----
        float s[8][4];
#pragma unroll
        for (int qi = 0; qi < 8; qi++)
#pragma unroll
            for (int ji = 0; ji < 4; ji++) s[qi][ji] = 0.f;

#pragma unroll 4
        for (int c = 0; c < DH; c++) {
            float rQ[8], rK[4];
            *(float4*)&rQ[0] = *(const float4*)&Qs[c * BQA + ty * 8];
            *(float4*)&rQ[4] = *(const float4*)&Qs[c * BQA + ty * 8 + 4];
            *(float4*)&rK[0] = *(const float4*)&Ks[c * BKA + tx * 4];
#pragma unroll
            for (int qi = 0; qi < 8; qi++)
#pragma unroll
                for (int ji = 0; ji < 4; ji++) s[qi][ji] += rQ[qi] * rK[ji];
        }

        // ---- online softmax (16 tx threads per q-row) ----
#pragma unroll
        for (int qi = 0; qi < 8; qi++) {
            float m = fmaxf(fmaxf(s[qi][0], s[qi][1]), fmaxf(s[qi][2], s[qi][3]));
            m = fmaxf(m, __shfl_xor_sync(0xffffffffu, m, 1));
            m = fmaxf(m, __shfl_xor_sync(0xffffffffu, m, 2));
            m = fmaxf(m, __shfl_xor_sync(0xffffffffu, m, 4));
            m = fmaxf(m, __shfl_xor_sync(0xffffffffu, m, 8));
            const float mnew = fmaxf(m_run[qi], m);
            const float corr = __expf(m_run[qi] - mnew);
            m_run[qi] = mnew;
            float p0 = __expf(s[qi][0] - mnew);
            float p1 = __expf(s[qi][1] - mnew);
            float p2 = __expf(s[qi][2] - mnew);
            float p3 = __expf(s[qi][3] - mnew);
            float ls = (p0 + p1) + (p2 + p3);
            ls += __shfl_xor_sync(0xffffffffu, ls, 1);
            ls += __shfl_xor_sync(0xffffffffu, ls, 2);
            ls += __shfl_xor_sync(0xffffffffu, ls, 4);
            ls += __shfl_xor_sync(0xffffffffu, ls, 8);
            l_run[qi] = l_run[qi] * corr + ls;
            if (tx == 0) corr_s[ty * 8 + qi] = corr;
            float4 pv;
            pv.x = p0; pv.y = p1; pv.z = p2; pv.w = p3;
            *(float4*)&Ps[(ty * 8 + qi) * PSTR + tx * 4] = pv;
        }
        __syncthreads();                   // Ps/corr visible; Ks reads done

        // issue K(t+1) (overlaps PV), then ensure V(t) resident
        if (t + 1 < nT) {
            const float* Kg2 = Kg + (size_t)(t + 1) * BKA;
#pragma unroll
            for (int i = 0; i < 10; i++) {
                int idx = tid + 256 * i;
                int c = idx >> 4, col = (idx & 15) * 4;
                cp_async16(&Ks[c * BKA + col], Kg2 + (size_t)c * SEQ + col);
            }
            CP_COMMIT();
            CP_WAIT1();                    // V(t) done (in-order retirement)
        } else {
            CP_WAIT0();                    // last tile: V(t) is the only group
        }
        __syncthreads();                   // all threads see V(t)

        // ---- PV: o[8][10] accumulate ----
        {
            float c8[8];
#pragma unroll
            for (int qi = 0; qi < 8; qi++) c8[qi] = corr_s[ty * 8 + qi];
#pragma unroll
            for (int qi = 0; qi < 8; qi++)
#pragma unroll
                for (int d = 0; d < 10; d++) o[qi][d] *= c8[qi];

#pragma unroll 2
            for (int j = 0; j < BKA; j++) {
                float p[8];
#pragma unroll
                for (int qi = 0; qi < 8; qi++)
                    p[qi] = Ps[(ty * 8 + qi) * PSTR + j];
                float v[10];
#pragma unroll
                for (int e = 0; e < 5; e++) {
                    float2 vv = *(const float2*)&Vs[j * DH + tx * 10 + e * 2];
                    v[e * 2] = vv.x; v[e * 2 + 1] = vv.y;
                }
#pragma unroll
                for (int qi = 0; qi < 8; qi++)
#pragma unroll
                    for (int d = 0; d < 10; d++) o[qi][d] += p[qi] * v[d];
            }
        }
        __syncthreads();                   // Vs reads done

        // issue V(t+1): overlaps next tile's score GEMM
        if (t + 1 < nT) {
            const float* Vg2 = Vg + (size_t)(t + 1) * BKA * HIDDEN;
#pragma unroll
            for (int i = 0; i < 10; i++) {
                int idx = tid + 256 * i;
                int j = idx / 40, col = (idx % 40) * 4;
                cp_async16(&Vs[j * DH + col], Vg2 + (size_t)j * HIDDEN + col);
            }
            CP_COMMIT();
        }
    }

    // final normalization (l_run replicated across tx; use local copy)
    if (tx == 0) {
#pragma unroll
        for (int qi = 0; qi < 8; qi++) l_s[ty * 8 + qi] = l_run[qi];
    }
    __syncthreads();

#pragma unroll
    for (int qi = 0; qi < 8; qi++) {
        const float inv = 1.f / l_s[ty * 8 + qi];
        float* Ob = O + ((size_t)(b * SEQ + q0 + ty * 8 + qi)) * HIDDEN
                      + h * DH + tx * 10;
#pragma unroll
        for (int e = 0; e < 5; e++) {
            float2 t2;
            t2.x = o[qi][e * 2] * inv;
            t2.y = o[qi][e * 2 + 1] * inv;
            *(float2*)(Ob + e * 2) = t2;
        }
    }
}

// ---------------- launch ----------------------------------------------------
extern "C" void kernel_launch(void* const* d_in, const int* in_sizes, int n_in,
                              void* d_out, int out_size)
{
    const float* x     = (const float*)d_in[0];
    const float* w_q   = (const float*)d_in[1];
    const float* w_k   = (const float*)d_in[2];
    const float* w_v   = (const float*)d_in[3];
    const float* lka   = (const float*)d_in[4];
    const float* lkb   = (const float*)d_in[5];
    const float* lva   = (const float*)d_in[6];
    const float* lvb   = (const float*)d_in[7];
    const float* w_out = (const float*)d_in[8];
    const float* b_out = (const float*)d_in[9];
    float* out = (float*)d_out;

    float *q_ptr, *k_ptr, *v_ptr, *o_ptr, *qt_ptr, *kt_ptr;
    cudaGetSymbolAddress((void**)&q_ptr, g_q);
    cudaGetSymbolAddress((void**)&k_ptr, g_k);
    cudaGetSymbolAddress((void**)&v_ptr, g_v);
    cudaGetSymbolAddress((void**)&o_ptr, g_o);
    cudaGetSymbolAddress((void**)&qt_ptr, g_qt);
    cudaGetSymbolAddress((void**)&kt_ptr, g_kt);

    cudaFuncSetAttribute(attn_kernel,
                         cudaFuncAttributeMaxDynamicSharedMemorySize,
                         ATTN_SMEM_BYTES);

    // fused QKV projections
    dim3 qkv_grid(HIDDEN / BN, MROWS / BM, 3);
    sgemm_qkv_kernel<<<qkv_grid, 256>>>(x, w_q, w_k, w_v, q_ptr, k_ptr, v_ptr);

    // LoRA rank-4 updates (in place)
    lora_kernel<<<MROWS, 128>>>(k_ptr, lka, lkb);
    lora_kernel<<<MROWS, 128>>>(v_ptr, lva, lvb);

    // transpose Q (scaled) and K to [bh][c][s]
    dim3 tgrid(SEQ / 32, DH / 32, BH * 2);
    transpose_qk_kernel<<<tgrid, dim3(32, 8)>>>(q_ptr, k_ptr, qt_ptr, kt_ptr);

    // attention
    dim3 agrid(SEQ / BQA, BH);
    attn_kernel<<<agrid, 256, ATTN_SMEM_BYTES>>>(qt_ptr, kt_ptr, v_ptr, o_ptr);

    // output projection + bias
    dim3 ggrid(HIDDEN / BN, MROWS / BM);
    sgemm_kernel<<<ggrid, 256>>>(o_ptr, w_out, b_out, out, MROWS, HIDDEN, HIDDEN);
}